// round 8
// baseline (speedup 1.0000x reference)
#include <cuda_runtime.h>
#include <cuda_bf16.h>

#define N_USERS 100000
#define N_ITEMS 50000
#define NN      150000
#define NE      2000000
#define DD      64
#define NB      16384
#define SB      586      // ceil(NN/256) scan blocks

// ---------------- scratch (device globals) ----------------------------------
__device__ float          g_x [NN*DD];    // layer outputs (fp32)
__device__ __nv_bfloat16  g_hb[NN*DD];    // h = x@W in bf16 (gather payload)
__device__ float g_as [NN*4];
__device__ float g_ad [NN*4];
__device__ int   g_adj[NE];
__device__ int   g_cnt[NN];
__device__ int   g_off[NN+1];
__device__ int   g_pos[NN];
__device__ int   g_perm[NN];
__device__ int   g_dbin[1024];
__device__ int   g_spine[1024];
__device__ int   g_is64;

// ---------------- helpers ---------------------------------------------------
__device__ __forceinline__ float lrelu(float x) { return x > 0.f ? x : 0.2f * x; }
__device__ __forceinline__ float eluf (float v) { return v > 0.f ? v : expf(v) - 1.f; }
__device__ __forceinline__ float2 bf2f(unsigned u) {
    return __bfloat1622float2(*(__nv_bfloat162*)&u);
}

// ---------------- init: zero counters + dtype detect -------------------------
__global__ void k_init(const int* __restrict__ ei) {
    int i = blockIdx.x * blockDim.x + threadIdx.x;
    if (i < NN) g_cnt[i] = 0;
    if (i < 1024) g_dbin[i] = 0;
    if (blockIdx.x == 0 && threadIdx.x == 0) {
        int all0 = 1;
        for (int k = 0; k < 64; k++)
            if (ei[2 * k + 1] != 0) { all0 = 0; break; }
        g_is64 = all0;
    }
}

__global__ void k_count(const void* __restrict__ ei) {
    int e = blockIdx.x * blockDim.x + threadIdx.x;
    if (e >= NE) return;
    int d = g_is64 ? (int)((const long long*)ei)[NE + e]
                   : ((const int*)ei)[NE + e];
    atomicAdd(&g_cnt[d], 1);
}

// block sums -> spine (shuffle reduce)
__global__ void k_s1() {
    __shared__ int ws[8];
    int t = threadIdx.x;
    int i = blockIdx.x * 256 + t;
    int v = (i < NN) ? g_cnt[i] : 0;
#pragma unroll
    for (int d = 16; d; d >>= 1) v += __shfl_xor_sync(0xffffffffu, v, d);
    if ((t & 31) == 0) ws[t >> 5] = v;
    __syncthreads();
    if (t < 8) {
        int s = ws[t];
#pragma unroll
        for (int d = 4; d; d >>= 1) s += __shfl_xor_sync(0xffu, s, d);
        if (t == 0) g_spine[blockIdx.x] = s;
    }
}

// generic 1024-wide exclusive scan (shuffle-based) on an int array
template <int NVALID>
__device__ __forceinline__ void scan1024(int* arr, int extra_flag) {
    __shared__ int ws[32];
    int t = threadIdx.x;
    int orig = (t < NVALID) ? arr[t] : 0;
    int v = orig;
#pragma unroll
    for (int d = 1; d < 32; d <<= 1) {
        int u = __shfl_up_sync(0xffffffffu, v, d);
        if ((t & 31) >= d) v += u;
    }
    if ((t & 31) == 31) ws[t >> 5] = v;
    __syncthreads();
    if (t < 32) {
        int s = ws[t];
#pragma unroll
        for (int d = 1; d < 32; d <<= 1) {
            int u = __shfl_up_sync(0xffffffffu, s, d);
            if (t >= d) s += u;
        }
        ws[t] = s;
    }
    __syncthreads();
    int incl = v + ((t >= 32) ? ws[(t >> 5) - 1] : 0);
    if (t < NVALID) arr[t] = incl - orig;
}

__global__ void k_s2() {
    scan1024<SB>(g_spine, 0);
    if (threadIdx.x == 0) g_off[NN] = NE;
}

// per-block exclusive scan + spine offset (shuffle-based)
__global__ void k_s3() {
    __shared__ int ws[8];
    int t = threadIdx.x;
    int i = blockIdx.x * 256 + t;
    int orig = (i < NN) ? g_cnt[i] : 0;
    int v = orig;
#pragma unroll
    for (int d = 1; d < 32; d <<= 1) {
        int u = __shfl_up_sync(0xffffffffu, v, d);
        if ((t & 31) >= d) v += u;
    }
    if ((t & 31) == 31) ws[t >> 5] = v;
    __syncthreads();
    if (t < 8) {
        int s = ws[t];
#pragma unroll
        for (int d = 1; d < 8; d <<= 1) {
            int u = __shfl_up_sync(0xffu, s, d);
            if (t >= d) s += u;
        }
        ws[t] = s;
    }
    __syncthreads();
    int incl = v + ((t >= 32) ? ws[(t >> 5) - 1] : 0);
    int excl = incl - orig + g_spine[blockIdx.x];
    if (i < NN) { g_off[i] = excl; g_pos[i] = excl; }
}

__global__ void k_scatter(const void* __restrict__ ei) {
    int e = blockIdx.x * blockDim.x + threadIdx.x;
    if (e >= NE) return;
    int s, d;
    if (g_is64) {
        const long long* p = (const long long*)ei;
        s = (int)p[e]; d = (int)p[NE + e];
    } else {
        const int* p = (const int*)ei;
        s = p[e]; d = p[NE + e];
    }
    int pos = atomicAdd(&g_pos[d], 1);
    g_adj[pos] = s;
}

// ---------------- degree sort (counting sort into g_perm) --------------------
__global__ void k_dhist() {
    int n = blockIdx.x * blockDim.x + threadIdx.x;
    if (n >= NN) return;
    int dg = g_cnt[n]; if (dg > 1023) dg = 1023;
    atomicAdd(&g_dbin[dg], 1);
}
__global__ void k_dscan() { scan1024<1024>(g_dbin, 0); }
__global__ void k_dperm() {
    int n = blockIdx.x * blockDim.x + threadIdx.x;
    if (n >= NN) return;
    int dg = g_cnt[n]; if (dg > 1023) dg = 1023;
    int pos = atomicAdd(&g_dbin[dg], 1);
    g_perm[pos] = n;
}

// ---------------- fused GEMM + alpha ------------------------------------------
// 128 threads, 64 nodes/block; thread = 4 nodes x 8 cols.
template <bool FIRST, int H>
__global__ void k_gemm(const float* __restrict__ W,
                       const float* __restrict__ ue,
                       const float* __restrict__ ie,
                       const float* __restrict__ a_src,
                       const float* __restrict__ a_dst) {
    __shared__ float sW[64 * 64];
    __shared__ float sxT[64][68];
    int t = threadIdx.x;
#pragma unroll
    for (int i = 0; i < 8; i++)
        *(float4*)&sW[(t + 128 * i) * 4] = *(const float4*)&W[(t + 128 * i) * 4];
    int n0 = blockIdx.x * 64;
#pragma unroll
    for (int i = 0; i < 8; i++) {
        int f = t + 128 * i;
        int node = f >> 4;
        int col  = (f & 15) * 4;
        int n = n0 + node;
        float4 v = make_float4(0.f, 0.f, 0.f, 0.f);
        if (n < NN) {
            const float* row = FIRST
                ? (n < N_USERS ? ue + (size_t)n * 64
                               : ie + (size_t)(n - N_USERS) * 64)
                : g_x + (size_t)n * 64;
            v = *(const float4*)(row + col);
        }
        sxT[col + 0][node] = v.x; sxT[col + 1][node] = v.y;
        sxT[col + 2][node] = v.z; sxT[col + 3][node] = v.w;
    }
    __syncthreads();
    int ng = t >> 3;
    int cg = t & 7;
    float acc[4][8];
#pragma unroll
    for (int i = 0; i < 4; i++)
#pragma unroll
        for (int j = 0; j < 8; j++) acc[i][j] = 0.f;
#pragma unroll 4
    for (int k = 0; k < 64; k++) {
        float4 xv = *(float4*)&sxT[k][ng * 4];
        float4 w0 = *(float4*)&sW[k * 64 + cg * 8];
        float4 w1 = *(float4*)&sW[k * 64 + cg * 8 + 4];
        float xi;
#pragma unroll
        for (int i = 0; i < 4; i++) {
            xi = (i == 0) ? xv.x : (i == 1) ? xv.y : (i == 2) ? xv.z : xv.w;
            acc[i][0] += xi * w0.x; acc[i][1] += xi * w0.y;
            acc[i][2] += xi * w0.z; acc[i][3] += xi * w0.w;
            acc[i][4] += xi * w1.x; acc[i][5] += xi * w1.y;
            acc[i][6] += xi * w1.z; acc[i][7] += xi * w1.w;
        }
    }
#pragma unroll
    for (int i = 0; i < 4; i++) {
        int n = n0 + ng * 4 + i;
        if (n < NN) {
            __nv_bfloat162 b0 = __float22bfloat162_rn(make_float2(acc[i][0], acc[i][1]));
            __nv_bfloat162 b1 = __float22bfloat162_rn(make_float2(acc[i][2], acc[i][3]));
            __nv_bfloat162 b2 = __float22bfloat162_rn(make_float2(acc[i][4], acc[i][5]));
            __nv_bfloat162 b3 = __float22bfloat162_rn(make_float2(acc[i][6], acc[i][7]));
            uint4 pk;
            pk.x = *(unsigned*)&b0; pk.y = *(unsigned*)&b1;
            pk.z = *(unsigned*)&b2; pk.w = *(unsigned*)&b3;
            *(uint4*)&g_hb[(size_t)n * 64 + cg * 8] = pk;
        }
    }
    float4 av0 = *(const float4*)&a_src[cg * 8];
    float4 av1 = *(const float4*)&a_src[cg * 8 + 4];
    float4 dv0 = *(const float4*)&a_dst[cg * 8];
    float4 dv1 = *(const float4*)&a_dst[cg * 8 + 4];
    float ps[4], pd[4];
#pragma unroll
    for (int i = 0; i < 4; i++) {
        ps[i] = acc[i][0]*av0.x + acc[i][1]*av0.y + acc[i][2]*av0.z + acc[i][3]*av0.w
              + acc[i][4]*av1.x + acc[i][5]*av1.y + acc[i][6]*av1.z + acc[i][7]*av1.w;
        pd[i] = acc[i][0]*dv0.x + acc[i][1]*dv0.y + acc[i][2]*dv0.z + acc[i][3]*dv0.w
              + acc[i][4]*dv1.x + acc[i][5]*dv1.y + acc[i][6]*dv1.z + acc[i][7]*dv1.w;
    }
    if (H == 4) {
#pragma unroll
        for (int i = 0; i < 4; i++) {
            ps[i] += __shfl_xor_sync(0xffffffffu, ps[i], 1);
            pd[i] += __shfl_xor_sync(0xffffffffu, pd[i], 1);
        }
        if ((cg & 1) == 0) {
            int head = cg >> 1;
#pragma unroll
            for (int i = 0; i < 4; i++) {
                int n = n0 + ng * 4 + i;
                if (n < NN) {
                    g_as[n * 4 + head] = ps[i];
                    g_ad[n * 4 + head] = pd[i];
                }
            }
        }
    } else {
#pragma unroll
        for (int i = 0; i < 4; i++) {
            ps[i] += __shfl_xor_sync(0xffffffffu, ps[i], 1);
            ps[i] += __shfl_xor_sync(0xffffffffu, ps[i], 2);
            ps[i] += __shfl_xor_sync(0xffffffffu, ps[i], 4);
            pd[i] += __shfl_xor_sync(0xffffffffu, pd[i], 1);
            pd[i] += __shfl_xor_sync(0xffffffffu, pd[i], 2);
            pd[i] += __shfl_xor_sync(0xffffffffu, pd[i], 4);
        }
        if (cg == 0) {
#pragma unroll
            for (int i = 0; i < 4; i++) {
                int n = n0 + ng * 4 + i;
                if (n < NN) { g_as[n] = ps[i]; g_ad[n] = pd[i]; }
            }
        }
    }
}

// ---------------- fused aggregation: EIGHT degree-matched nodes per warp -----
// Nodes taken in degree-sorted order via g_perm so the 8 nodes in a warp have
// (near-)equal degree -> no divergence waste. 4 lanes per node; lane owns
// 16 cols (2x uint4 bf16). 8 independent chains per warp instruction.
template <int H, int F>
__global__ void __launch_bounds__(256) k_agg(const float* __restrict__ b) {
    int lane = threadIdx.x & 31;
    int wrp  = threadIdx.x >> 5;
    int sub  = lane >> 2;          // node slot within warp (0..7)
    int l    = lane & 3;           // lane within node (0..3)
    int idx  = blockIdx.x * 64 + wrp * 8 + sub;
    if (idx >= NN) return;
    int n = g_perm[idx];
    int c0   = l * 16;
    int head = c0 / F;             // H=4: head==l ; H=1: 0

    float ad_d = __ldg(&g_ad[(size_t)n * H + head]);
    float den  = __expf(lrelu(__ldg(&g_as[(size_t)n * H + head]) + ad_d));
    const uint4* hb = (const uint4*)g_hb;      // row = 8 uint4 (64 bf16)
    float a[16];
    {
        uint4 hA = hb[(size_t)n * 8 + l * 2];
        uint4 hB = hb[(size_t)n * 8 + l * 2 + 1];
        float2 f0 = bf2f(hA.x), f1 = bf2f(hA.y), f2 = bf2f(hA.z), f3 = bf2f(hA.w);
        float2 f4 = bf2f(hB.x), f5 = bf2f(hB.y), f6 = bf2f(hB.z), f7 = bf2f(hB.w);
        a[0]=den*f0.x; a[1]=den*f0.y; a[2]=den*f1.x; a[3]=den*f1.y;
        a[4]=den*f2.x; a[5]=den*f2.y; a[6]=den*f3.x; a[7]=den*f3.y;
        a[8]=den*f4.x; a[9]=den*f4.y; a[10]=den*f5.x; a[11]=den*f5.y;
        a[12]=den*f6.x; a[13]=den*f6.y; a[14]=den*f7.x; a[15]=den*f7.y;
    }

    int beg = g_off[n], end = g_off[n + 1];
    int j = beg;
    for (; j + 2 <= end; j += 2) {
        int s0 = __ldg(&g_adj[j + 0]);
        int s1 = __ldg(&g_adj[j + 1]);
        float w0 = __expf(lrelu(__ldg(&g_as[(size_t)s0 * H + head]) + ad_d));
        float w1 = __expf(lrelu(__ldg(&g_as[(size_t)s1 * H + head]) + ad_d));
        uint4 pA0 = hb[(size_t)s0 * 8 + l * 2];
        uint4 pB0 = hb[(size_t)s0 * 8 + l * 2 + 1];
        uint4 pA1 = hb[(size_t)s1 * 8 + l * 2];
        uint4 pB1 = hb[(size_t)s1 * 8 + l * 2 + 1];
        den += w0 + w1;
        {
            float2 f0 = bf2f(pA0.x), f1 = bf2f(pA0.y), f2 = bf2f(pA0.z), f3 = bf2f(pA0.w);
            float2 f4 = bf2f(pB0.x), f5 = bf2f(pB0.y), f6 = bf2f(pB0.z), f7 = bf2f(pB0.w);
            a[0]+=w0*f0.x; a[1]+=w0*f0.y; a[2]+=w0*f1.x; a[3]+=w0*f1.y;
            a[4]+=w0*f2.x; a[5]+=w0*f2.y; a[6]+=w0*f3.x; a[7]+=w0*f3.y;
            a[8]+=w0*f4.x; a[9]+=w0*f4.y; a[10]+=w0*f5.x; a[11]+=w0*f5.y;
            a[12]+=w0*f6.x; a[13]+=w0*f6.y; a[14]+=w0*f7.x; a[15]+=w0*f7.y;
        }
        {
            float2 f0 = bf2f(pA1.x), f1 = bf2f(pA1.y), f2 = bf2f(pA1.z), f3 = bf2f(pA1.w);
            float2 f4 = bf2f(pB1.x), f5 = bf2f(pB1.y), f6 = bf2f(pB1.z), f7 = bf2f(pB1.w);
            a[0]+=w1*f0.x; a[1]+=w1*f0.y; a[2]+=w1*f1.x; a[3]+=w1*f1.y;
            a[4]+=w1*f2.x; a[5]+=w1*f2.y; a[6]+=w1*f3.x; a[7]+=w1*f3.y;
            a[8]+=w1*f4.x; a[9]+=w1*f4.y; a[10]+=w1*f5.x; a[11]+=w1*f5.y;
            a[12]+=w1*f6.x; a[13]+=w1*f6.y; a[14]+=w1*f7.x; a[15]+=w1*f7.y;
        }
    }
    for (; j < end; j++) {
        int s = __ldg(&g_adj[j]);
        float w = __expf(lrelu(__ldg(&g_as[(size_t)s * H + head]) + ad_d));
        uint4 pA = hb[(size_t)s * 8 + l * 2];
        uint4 pB = hb[(size_t)s * 8 + l * 2 + 1];
        float2 f0 = bf2f(pA.x), f1 = bf2f(pA.y), f2 = bf2f(pA.z), f3 = bf2f(pA.w);
        float2 f4 = bf2f(pB.x), f5 = bf2f(pB.y), f6 = bf2f(pB.z), f7 = bf2f(pB.w);
        den += w;
        a[0]+=w*f0.x; a[1]+=w*f0.y; a[2]+=w*f1.x; a[3]+=w*f1.y;
        a[4]+=w*f2.x; a[5]+=w*f2.y; a[6]+=w*f3.x; a[7]+=w*f3.y;
        a[8]+=w*f4.x; a[9]+=w*f4.y; a[10]+=w*f5.x; a[11]+=w*f5.y;
        a[12]+=w*f6.x; a[13]+=w*f6.y; a[14]+=w*f7.x; a[15]+=w*f7.y;
    }
    float inv = 1.f / den;
    float* xr = &g_x[(size_t)n * 64 + c0];
#pragma unroll
    for (int q = 0; q < 4; q++) {
        float4 o;
        o.x = eluf(a[q*4+0] * inv + b[c0 + q*4 + 0]);
        o.y = eluf(a[q*4+1] * inv + b[c0 + q*4 + 1]);
        o.z = eluf(a[q*4+2] * inv + b[c0 + q*4 + 2]);
        o.w = eluf(a[q*4+3] * inv + b[c0 + q*4 + 3]);
        *(float4*)&xr[q*4] = o;
    }
}

// ---------------- final scoring ----------------------------------------------
__global__ void k_score(const void* __restrict__ bu_, const void* __restrict__ bi_,
                        float* __restrict__ out) {
    int gid = blockIdx.x * blockDim.x + threadIdx.x;
    if (gid >= NB * 8) return;
    int p = gid >> 3, l = gid & 7;
    int u, it;
    if (g_is64) {
        u  = (int)((const long long*)bu_)[p];
        it = (int)((const long long*)bi_)[p];
    } else {
        u  = ((const int*)bu_)[p];
        it = ((const int*)bi_)[p];
    }
    const float* xu = &g_x[(long)u * 64];
    const float* xv = &g_x[((long)it + N_USERS) * 64];
    int o = l * 8;
    float acc = 0.f;
#pragma unroll
    for (int k = 0; k < 8; k++) acc += xu[o + k] * xv[o + k];
    acc += __shfl_xor_sync(0xffffffffu, acc, 1);
    acc += __shfl_xor_sync(0xffffffffu, acc, 2);
    acc += __shfl_xor_sync(0xffffffffu, acc, 4);
    if (l == 0) out[p] = 1.f / (1.f + expf(-acc));
}

// ---------------- host launcher ----------------------------------------------
extern "C" void kernel_launch(void* const* d_in, const int* in_sizes, int n_in,
                              void* d_out, int out_size) {
    const void *edge = nullptr, *bu = nullptr, *bi = nullptr;
    const float *ue = nullptr, *ie = nullptr, *W1 = nullptr, *W2 = nullptr;
    const float* v64[6] = {nullptr, nullptr, nullptr, nullptr, nullptr, nullptr};
    int c64 = 0;
    for (int i = 0; i < n_in; i++) {
        int sz = in_sizes[i];
        if      (sz == 2 * NE)        edge = d_in[i];
        else if (sz == NB)            { if (!bu) bu = d_in[i]; else bi = d_in[i]; }
        else if (sz == N_USERS * DD)  ue = (const float*)d_in[i];
        else if (sz == N_ITEMS * DD)  ie = (const float*)d_in[i];
        else if (sz == DD * DD)       { if (!W1) W1 = (const float*)d_in[i];
                                        else     W2 = (const float*)d_in[i]; }
        else if (sz == 64 && c64 < 6) v64[c64++] = (const float*)d_in[i];
    }
    const float *as1 = v64[0], *ad1 = v64[1], *b1 = v64[2];
    const float *as2 = v64[3], *ad2 = v64[4], *b2 = v64[5];

    const int TB = 256;
    const int EB = (NE + TB - 1) / TB;

    k_init   <<<(NN + TB - 1) / TB, TB>>>((const int*)edge);
    k_count  <<<EB, TB>>>(edge);
    k_s1     <<<SB, 256>>>();
    k_s2     <<<1, 1024>>>();
    k_s3     <<<SB, 256>>>();
    k_scatter<<<EB, TB>>>(edge);
    k_dhist  <<<(NN + TB - 1) / TB, TB>>>();
    k_dscan  <<<1, 1024>>>();
    k_dperm  <<<(NN + TB - 1) / TB, TB>>>();

    // ---- layer 1: H=4, F=16 ----
    k_gemm<true, 4> <<<(NN + 63) / 64, 128>>>(W1, ue, ie, as1, ad1);
    k_agg <4, 16>   <<<(NN + 63) / 64, TB>>>(b1);

    // ---- layer 2: H=1, F=64 ----
    k_gemm<false, 1><<<(NN + 63) / 64, 128>>>(W2, nullptr, nullptr, as2, ad2);
    k_agg <1, 64>   <<<(NN + 63) / 64, TB>>>(b2);

    k_score<<<(NB * 8 + TB - 1) / TB, TB>>>(bu, bi, (float*)d_out);
}

// round 10
// speedup vs baseline: 1.0391x; 1.0391x over previous
#include <cuda_runtime.h>
#include <cuda_bf16.h>

#define N_USERS 100000
#define N_ITEMS 50000
#define NN      150000
#define NE      2000000
#define DD      64
#define NB      16384
#define SB      586      // ceil(NN/256) scan blocks

// ---------------- scratch (device globals) ----------------------------------
__device__ float          g_x [NN*DD];    // layer outputs (fp32)
__device__ __nv_bfloat16  g_hb[NN*DD];    // h = x@W in bf16 (gather payload)
__device__ float g_as [NN*4];
__device__ float g_ad [NN*4];
__device__ int   g_adj[NE];
__device__ int   g_cnt[NN];
__device__ int   g_off[NN+1];
__device__ int   g_pos[NN];
__device__ int   g_perm[NN];
__device__ int   g_dbin[1024];
__device__ int   g_spine[1024];
__device__ int   g_is64;

// ---------------- helpers ---------------------------------------------------
__device__ __forceinline__ float lrelu(float x) { return x > 0.f ? x : 0.2f * x; }
__device__ __forceinline__ float eluf (float v) { return v > 0.f ? v : expf(v) - 1.f; }
__device__ __forceinline__ float2 bf2f(unsigned u) {
    return __bfloat1622float2(*(__nv_bfloat162*)&u);
}

// ---------------- init: zero counters + dtype detect -------------------------
__global__ void k_init(const int* __restrict__ ei) {
    int i = blockIdx.x * blockDim.x + threadIdx.x;
    if (i < NN) g_cnt[i] = 0;
    if (i < 1024) g_dbin[i] = 0;
    if (blockIdx.x == 0 && threadIdx.x == 0) {
        int all0 = 1;
        for (int k = 0; k < 64; k++)
            if (ei[2 * k + 1] != 0) { all0 = 0; break; }
        g_is64 = all0;
    }
}

__global__ void k_count(const void* __restrict__ ei) {
    int e = blockIdx.x * blockDim.x + threadIdx.x;
    if (e >= NE) return;
    int d = g_is64 ? (int)((const long long*)ei)[NE + e]
                   : ((const int*)ei)[NE + e];
    atomicAdd(&g_cnt[d], 1);
}

// block sums -> spine (shuffle reduce)
__global__ void k_s1() {
    __shared__ int ws[8];
    int t = threadIdx.x;
    int i = blockIdx.x * 256 + t;
    int v = (i < NN) ? g_cnt[i] : 0;
#pragma unroll
    for (int d = 16; d; d >>= 1) v += __shfl_xor_sync(0xffffffffu, v, d);
    if ((t & 31) == 0) ws[t >> 5] = v;
    __syncthreads();
    if (t < 8) {
        int s = ws[t];
#pragma unroll
        for (int d = 4; d; d >>= 1) s += __shfl_xor_sync(0xffu, s, d);
        if (t == 0) g_spine[blockIdx.x] = s;
    }
}

// generic 1024-wide exclusive scan (shuffle-based) on an int array
template <int NVALID>
__device__ __forceinline__ void scan1024(int* arr) {
    __shared__ int ws[32];
    int t = threadIdx.x;
    int orig = (t < NVALID) ? arr[t] : 0;
    int v = orig;
#pragma unroll
    for (int d = 1; d < 32; d <<= 1) {
        int u = __shfl_up_sync(0xffffffffu, v, d);
        if ((t & 31) >= d) v += u;
    }
    if ((t & 31) == 31) ws[t >> 5] = v;
    __syncthreads();
    if (t < 32) {
        int s = ws[t];
#pragma unroll
        for (int d = 1; d < 32; d <<= 1) {
            int u = __shfl_up_sync(0xffffffffu, s, d);
            if (t >= d) s += u;
        }
        ws[t] = s;
    }
    __syncthreads();
    int incl = v + ((t >= 32) ? ws[(t >> 5) - 1] : 0);
    if (t < NVALID) arr[t] = incl - orig;
}

__global__ void k_s2() {
    scan1024<SB>(g_spine);
    if (threadIdx.x == 0) g_off[NN] = NE;
}

// per-block exclusive scan + spine offset (shuffle-based)
__global__ void k_s3() {
    __shared__ int ws[8];
    int t = threadIdx.x;
    int i = blockIdx.x * 256 + t;
    int orig = (i < NN) ? g_cnt[i] : 0;
    int v = orig;
#pragma unroll
    for (int d = 1; d < 32; d <<= 1) {
        int u = __shfl_up_sync(0xffffffffu, v, d);
        if ((t & 31) >= d) v += u;
    }
    if ((t & 31) == 31) ws[t >> 5] = v;
    __syncthreads();
    if (t < 8) {
        int s = ws[t];
#pragma unroll
        for (int d = 1; d < 8; d <<= 1) {
            int u = __shfl_up_sync(0xffu, s, d);
            if (t >= d) s += u;
        }
        ws[t] = s;
    }
    __syncthreads();
    int incl = v + ((t >= 32) ? ws[(t >> 5) - 1] : 0);
    int excl = incl - orig + g_spine[blockIdx.x];
    if (i < NN) { g_off[i] = excl; g_pos[i] = excl; }
}

__global__ void k_scatter(const void* __restrict__ ei) {
    int e = blockIdx.x * blockDim.x + threadIdx.x;
    if (e >= NE) return;
    int s, d;
    if (g_is64) {
        const long long* p = (const long long*)ei;
        s = (int)p[e]; d = (int)p[NE + e];
    } else {
        const int* p = (const int*)ei;
        s = p[e]; d = p[NE + e];
    }
    int pos = atomicAdd(&g_pos[d], 1);
    g_adj[pos] = s;
}

// ---------------- degree sort (counting sort into g_perm) --------------------
__global__ void k_dhist() {
    int n = blockIdx.x * blockDim.x + threadIdx.x;
    if (n >= NN) return;
    int dg = g_cnt[n]; if (dg > 1023) dg = 1023;
    atomicAdd(&g_dbin[dg], 1);
}
__global__ void k_dscan() { scan1024<1024>(g_dbin); }
__global__ void k_dperm() {
    int n = blockIdx.x * blockDim.x + threadIdx.x;
    if (n >= NN) return;
    int dg = g_cnt[n]; if (dg > 1023) dg = 1023;
    int pos = atomicAdd(&g_dbin[dg], 1);
    g_perm[pos] = n;
}

// ---------------- fused GEMM + alpha ------------------------------------------
// 128 threads, 64 nodes/block; thread = 4 nodes x 8 cols.
template <bool FIRST, int H>
__global__ void k_gemm(const float* __restrict__ W,
                       const float* __restrict__ ue,
                       const float* __restrict__ ie,
                       const float* __restrict__ a_src,
                       const float* __restrict__ a_dst) {
    __shared__ float sW[64 * 64];
    __shared__ float sxT[64][68];
    int t = threadIdx.x;
#pragma unroll
    for (int i = 0; i < 8; i++)
        *(float4*)&sW[(t + 128 * i) * 4] = *(const float4*)&W[(t + 128 * i) * 4];
    int n0 = blockIdx.x * 64;
#pragma unroll
    for (int i = 0; i < 8; i++) {
        int f = t + 128 * i;
        int node = f >> 4;
        int col  = (f & 15) * 4;
        int n = n0 + node;
        float4 v = make_float4(0.f, 0.f, 0.f, 0.f);
        if (n < NN) {
            const float* row = FIRST
                ? (n < N_USERS ? ue + (size_t)n * 64
                               : ie + (size_t)(n - N_USERS) * 64)
                : g_x + (size_t)n * 64;
            v = *(const float4*)(row + col);
        }
        sxT[col + 0][node] = v.x; sxT[col + 1][node] = v.y;
        sxT[col + 2][node] = v.z; sxT[col + 3][node] = v.w;
    }
    __syncthreads();
    int ng = t >> 3;
    int cg = t & 7;
    float acc[4][8];
#pragma unroll
    for (int i = 0; i < 4; i++)
#pragma unroll
        for (int j = 0; j < 8; j++) acc[i][j] = 0.f;
#pragma unroll 4
    for (int k = 0; k < 64; k++) {
        float4 xv = *(float4*)&sxT[k][ng * 4];
        float4 w0 = *(float4*)&sW[k * 64 + cg * 8];
        float4 w1 = *(float4*)&sW[k * 64 + cg * 8 + 4];
        float xi;
#pragma unroll
        for (int i = 0; i < 4; i++) {
            xi = (i == 0) ? xv.x : (i == 1) ? xv.y : (i == 2) ? xv.z : xv.w;
            acc[i][0] += xi * w0.x; acc[i][1] += xi * w0.y;
            acc[i][2] += xi * w0.z; acc[i][3] += xi * w0.w;
            acc[i][4] += xi * w1.x; acc[i][5] += xi * w1.y;
            acc[i][6] += xi * w1.z; acc[i][7] += xi * w1.w;
        }
    }
#pragma unroll
    for (int i = 0; i < 4; i++) {
        int n = n0 + ng * 4 + i;
        if (n < NN) {
            __nv_bfloat162 b0 = __float22bfloat162_rn(make_float2(acc[i][0], acc[i][1]));
            __nv_bfloat162 b1 = __float22bfloat162_rn(make_float2(acc[i][2], acc[i][3]));
            __nv_bfloat162 b2 = __float22bfloat162_rn(make_float2(acc[i][4], acc[i][5]));
            __nv_bfloat162 b3 = __float22bfloat162_rn(make_float2(acc[i][6], acc[i][7]));
            uint4 pk;
            pk.x = *(unsigned*)&b0; pk.y = *(unsigned*)&b1;
            pk.z = *(unsigned*)&b2; pk.w = *(unsigned*)&b3;
            *(uint4*)&g_hb[(size_t)n * 64 + cg * 8] = pk;
        }
    }
    float4 av0 = *(const float4*)&a_src[cg * 8];
    float4 av1 = *(const float4*)&a_src[cg * 8 + 4];
    float4 dv0 = *(const float4*)&a_dst[cg * 8];
    float4 dv1 = *(const float4*)&a_dst[cg * 8 + 4];
    float ps[4], pd[4];
#pragma unroll
    for (int i = 0; i < 4; i++) {
        ps[i] = acc[i][0]*av0.x + acc[i][1]*av0.y + acc[i][2]*av0.z + acc[i][3]*av0.w
              + acc[i][4]*av1.x + acc[i][5]*av1.y + acc[i][6]*av1.z + acc[i][7]*av1.w;
        pd[i] = acc[i][0]*dv0.x + acc[i][1]*dv0.y + acc[i][2]*dv0.z + acc[i][3]*dv0.w
              + acc[i][4]*dv1.x + acc[i][5]*dv1.y + acc[i][6]*dv1.z + acc[i][7]*dv1.w;
    }
    if (H == 4) {
#pragma unroll
        for (int i = 0; i < 4; i++) {
            ps[i] += __shfl_xor_sync(0xffffffffu, ps[i], 1);
            pd[i] += __shfl_xor_sync(0xffffffffu, pd[i], 1);
        }
        if ((cg & 1) == 0) {
            int head = cg >> 1;
#pragma unroll
            for (int i = 0; i < 4; i++) {
                int n = n0 + ng * 4 + i;
                if (n < NN) {
                    g_as[n * 4 + head] = ps[i];
                    g_ad[n * 4 + head] = pd[i];
                }
            }
        }
    } else {
#pragma unroll
        for (int i = 0; i < 4; i++) {
            ps[i] += __shfl_xor_sync(0xffffffffu, ps[i], 1);
            ps[i] += __shfl_xor_sync(0xffffffffu, ps[i], 2);
            ps[i] += __shfl_xor_sync(0xffffffffu, ps[i], 4);
            pd[i] += __shfl_xor_sync(0xffffffffu, pd[i], 1);
            pd[i] += __shfl_xor_sync(0xffffffffu, pd[i], 2);
            pd[i] += __shfl_xor_sync(0xffffffffu, pd[i], 4);
        }
        if (cg == 0) {
#pragma unroll
            for (int i = 0; i < 4; i++) {
                int n = n0 + ng * 4 + i;
                if (n < NN) { g_as[n] = ps[i]; g_ad[n] = pd[i]; }
            }
        }
    }
}

// ---------------- fused aggregation: FOUR degree-matched nodes per warp ------
// Round-7 shape (known good: 8 accs, uint4 = full 128B row wavefront per node)
// + degree-sorted assignment via g_perm so the 4 nodes in a quarter-warp group
// have near-equal degree (no divergence waste).
template <int H, int F>
__global__ void k_agg(const float* __restrict__ b) {
    int lane = threadIdx.x & 31;
    int wrp  = threadIdx.x >> 5;
    int quad = lane >> 3;
    int l    = lane & 7;
    int idx  = blockIdx.x * 32 + wrp * 4 + quad;
    if (idx >= NN) return;
    int n = g_perm[idx];
    int c0   = l * 8;
    int head = c0 / F;

    float ad_d = __ldg(&g_ad[(size_t)n * H + head]);
    float den  = __expf(lrelu(__ldg(&g_as[(size_t)n * H + head]) + ad_d));
    const uint4* hb = (const uint4*)g_hb;          // row = 8 uint4 (64 bf16)
    uint4 hs = hb[(size_t)n * 8 + l];
    float2 h01 = bf2f(hs.x), h23 = bf2f(hs.y), h45 = bf2f(hs.z), h67 = bf2f(hs.w);
    float a0 = den * h01.x, a1 = den * h01.y, a2 = den * h23.x, a3 = den * h23.y;
    float a4 = den * h45.x, a5 = den * h45.y, a6 = den * h67.x, a7 = den * h67.y;

    int beg = g_off[n], end = g_off[n + 1];
    int j = beg;
    for (; j + 4 <= end; j += 4) {
        int s[4]; float w[4]; uint4 p[4];
#pragma unroll
        for (int q = 0; q < 4; q++) s[q] = __ldg(&g_adj[j + q]);
#pragma unroll
        for (int q = 0; q < 4; q++)
            w[q] = __expf(lrelu(__ldg(&g_as[(size_t)s[q] * H + head]) + ad_d));
#pragma unroll
        for (int q = 0; q < 4; q++) p[q] = hb[(size_t)s[q] * 8 + l];
#pragma unroll
        for (int q = 0; q < 4; q++) {
            float2 q01 = bf2f(p[q].x), q23 = bf2f(p[q].y);
            float2 q45 = bf2f(p[q].z), q67 = bf2f(p[q].w);
            den += w[q];
            a0 += w[q] * q01.x; a1 += w[q] * q01.y;
            a2 += w[q] * q23.x; a3 += w[q] * q23.y;
            a4 += w[q] * q45.x; a5 += w[q] * q45.y;
            a6 += w[q] * q67.x; a7 += w[q] * q67.y;
        }
    }
    for (; j < end; j++) {
        int s = __ldg(&g_adj[j]);
        float w = __expf(lrelu(__ldg(&g_as[(size_t)s * H + head]) + ad_d));
        uint4 p = hb[(size_t)s * 8 + l];
        float2 q01 = bf2f(p.x), q23 = bf2f(p.y), q45 = bf2f(p.z), q67 = bf2f(p.w);
        den += w;
        a0 += w * q01.x; a1 += w * q01.y; a2 += w * q23.x; a3 += w * q23.y;
        a4 += w * q45.x; a5 += w * q45.y; a6 += w * q67.x; a7 += w * q67.y;
    }
    float inv = 1.f / den;
    float4 o0, o1;
    o0.x = eluf(a0 * inv + b[c0 + 0]);
    o0.y = eluf(a1 * inv + b[c0 + 1]);
    o0.z = eluf(a2 * inv + b[c0 + 2]);
    o0.w = eluf(a3 * inv + b[c0 + 3]);
    o1.x = eluf(a4 * inv + b[c0 + 4]);
    o1.y = eluf(a5 * inv + b[c0 + 5]);
    o1.z = eluf(a6 * inv + b[c0 + 6]);
    o1.w = eluf(a7 * inv + b[c0 + 7]);
    *(float4*)&g_x[(size_t)n * 64 + c0]     = o0;
    *(float4*)&g_x[(size_t)n * 64 + c0 + 4] = o1;
}

// ---------------- final scoring ----------------------------------------------
__global__ void k_score(const void* __restrict__ bu_, const void* __restrict__ bi_,
                        float* __restrict__ out) {
    int gid = blockIdx.x * blockDim.x + threadIdx.x;
    if (gid >= NB * 8) return;
    int p = gid >> 3, l = gid & 7;
    int u, it;
    if (g_is64) {
        u  = (int)((const long long*)bu_)[p];
        it = (int)((const long long*)bi_)[p];
    } else {
        u  = ((const int*)bu_)[p];
        it = ((const int*)bi_)[p];
    }
    const float* xu = &g_x[(long)u * 64];
    const float* xv = &g_x[((long)it + N_USERS) * 64];
    int o = l * 8;
    float acc = 0.f;
#pragma unroll
    for (int k = 0; k < 8; k++) acc += xu[o + k] * xv[o + k];
    acc += __shfl_xor_sync(0xffffffffu, acc, 1);
    acc += __shfl_xor_sync(0xffffffffu, acc, 2);
    acc += __shfl_xor_sync(0xffffffffu, acc, 4);
    if (l == 0) out[p] = 1.f / (1.f + expf(-acc));
}

// ---------------- host launcher ----------------------------------------------
extern "C" void kernel_launch(void* const* d_in, const int* in_sizes, int n_in,
                              void* d_out, int out_size) {
    const void *edge = nullptr, *bu = nullptr, *bi = nullptr;
    const float *ue = nullptr, *ie = nullptr, *W1 = nullptr, *W2 = nullptr;
    const float* v64[6] = {nullptr, nullptr, nullptr, nullptr, nullptr, nullptr};
    int c64 = 0;
    for (int i = 0; i < n_in; i++) {
        int sz = in_sizes[i];
        if      (sz == 2 * NE)        edge = d_in[i];
        else if (sz == NB)            { if (!bu) bu = d_in[i]; else bi = d_in[i]; }
        else if (sz == N_USERS * DD)  ue = (const float*)d_in[i];
        else if (sz == N_ITEMS * DD)  ie = (const float*)d_in[i];
        else if (sz == DD * DD)       { if (!W1) W1 = (const float*)d_in[i];
                                        else     W2 = (const float*)d_in[i]; }
        else if (sz == 64 && c64 < 6) v64[c64++] = (const float*)d_in[i];
    }
    const float *as1 = v64[0], *ad1 = v64[1], *b1 = v64[2];
    const float *as2 = v64[3], *ad2 = v64[4], *b2 = v64[5];

    const int TB = 256;
    const int EB = (NE + TB - 1) / TB;

    k_init   <<<(NN + TB - 1) / TB, TB>>>((const int*)edge);
    k_count  <<<EB, TB>>>(edge);
    k_s1     <<<SB, 256>>>();
    k_s2     <<<1, 1024>>>();
    k_s3     <<<SB, 256>>>();
    k_scatter<<<EB, TB>>>(edge);
    k_dhist  <<<(NN + TB - 1) / TB, TB>>>();
    k_dscan  <<<1, 1024>>>();
    k_dperm  <<<(NN + TB - 1) / TB, TB>>>();

    // ---- layer 1: H=4, F=16 ----
    k_gemm<true, 4> <<<(NN + 63) / 64, 128>>>(W1, ue, ie, as1, ad1);
    k_agg <4, 16>   <<<(NN + 31) / 32, TB>>>(b1);

    // ---- layer 2: H=1, F=64 ----
    k_gemm<false, 1><<<(NN + 63) / 64, 128>>>(W2, nullptr, nullptr, as2, ad2);
    k_agg <1, 64>   <<<(NN + 31) / 32, TB>>>(b2);

    k_score<<<(NB * 8 + TB - 1) / TB, TB>>>(bu, bi, (float*)d_out);
}

// round 11
// speedup vs baseline: 1.2114x; 1.1658x over previous
#include <cuda_runtime.h>
#include <cuda_bf16.h>

#define N_USERS 100000
#define N_ITEMS 50000
#define NN      150000
#define NE      2000000
#define DD      64
#define NB      16384
#define SB      586      // ceil(NN/256) scan blocks

// ---------------- scratch (device globals) ----------------------------------
__device__ float          g_x [NN*DD];    // layer outputs (fp32)
__device__ __nv_bfloat16  g_hb[NN*DD];    // h = x@W in bf16 (gather payload)
__device__ float g_as [NN*4];
__device__ float g_ad [NN*4];
__device__ int   g_adj[NE];
__device__ int   g_cnt[NN];
__device__ int   g_off[NN+1];
__device__ int   g_pos[NN];
__device__ int   g_spine[1024];
__device__ int   g_is64;

// ---------------- helpers ---------------------------------------------------
__device__ __forceinline__ float lrelu(float x) { return x > 0.f ? x : 0.2f * x; }
__device__ __forceinline__ float eluf (float v) { return v > 0.f ? v : expf(v) - 1.f; }
__device__ __forceinline__ float2 bf2f(unsigned u) {
    return __bfloat1622float2(*(__nv_bfloat162*)&u);
}

// ---------------- init: zero counters + dtype detect -------------------------
__global__ void k_init(const int* __restrict__ ei) {
    int i = blockIdx.x * blockDim.x + threadIdx.x;
    if (i < NN) g_cnt[i] = 0;
    if (blockIdx.x == 0 && threadIdx.x == 0) {
        int all0 = 1;
        for (int k = 0; k < 64; k++)
            if (ei[2 * k + 1] != 0) { all0 = 0; break; }
        g_is64 = all0;
    }
}

__global__ void k_count(const void* __restrict__ ei) {
    int e = blockIdx.x * blockDim.x + threadIdx.x;
    if (e >= NE) return;
    int d = g_is64 ? (int)((const long long*)ei)[NE + e]
                   : ((const int*)ei)[NE + e];
    atomicAdd(&g_cnt[d], 1);
}

// block sums -> spine (shuffle reduce)
__global__ void k_s1() {
    __shared__ int ws[8];
    int t = threadIdx.x;
    int i = blockIdx.x * 256 + t;
    int v = (i < NN) ? g_cnt[i] : 0;
#pragma unroll
    for (int d = 16; d; d >>= 1) v += __shfl_xor_sync(0xffffffffu, v, d);
    if ((t & 31) == 0) ws[t >> 5] = v;
    __syncthreads();
    if (t < 8) {
        int s = ws[t];
#pragma unroll
        for (int d = 4; d; d >>= 1) s += __shfl_xor_sync(0xffu, s, d);
        if (t == 0) g_spine[blockIdx.x] = s;
    }
}

// 1024-wide exclusive scan (shuffle-based)
template <int NVALID>
__device__ __forceinline__ void scan1024(int* arr) {
    __shared__ int ws[32];
    int t = threadIdx.x;
    int orig = (t < NVALID) ? arr[t] : 0;
    int v = orig;
#pragma unroll
    for (int d = 1; d < 32; d <<= 1) {
        int u = __shfl_up_sync(0xffffffffu, v, d);
        if ((t & 31) >= d) v += u;
    }
    if ((t & 31) == 31) ws[t >> 5] = v;
    __syncthreads();
    if (t < 32) {
        int s = ws[t];
#pragma unroll
        for (int d = 1; d < 32; d <<= 1) {
            int u = __shfl_up_sync(0xffffffffu, s, d);
            if (t >= d) s += u;
        }
        ws[t] = s;
    }
    __syncthreads();
    int incl = v + ((t >= 32) ? ws[(t >> 5) - 1] : 0);
    if (t < NVALID) arr[t] = incl - orig;
}

__global__ void k_s2() {
    scan1024<SB>(g_spine);
    if (threadIdx.x == 0) g_off[NN] = NE;
}

// per-block exclusive scan + spine offset (shuffle-based)
__global__ void k_s3() {
    __shared__ int ws[8];
    int t = threadIdx.x;
    int i = blockIdx.x * 256 + t;
    int orig = (i < NN) ? g_cnt[i] : 0;
    int v = orig;
#pragma unroll
    for (int d = 1; d < 32; d <<= 1) {
        int u = __shfl_up_sync(0xffffffffu, v, d);
        if ((t & 31) >= d) v += u;
    }
    if ((t & 31) == 31) ws[t >> 5] = v;
    __syncthreads();
    if (t < 8) {
        int s = ws[t];
#pragma unroll
        for (int d = 1; d < 8; d <<= 1) {
            int u = __shfl_up_sync(0xffu, s, d);
            if (t >= d) s += u;
        }
        ws[t] = s;
    }
    __syncthreads();
    int incl = v + ((t >= 32) ? ws[(t >> 5) - 1] : 0);
    int excl = incl - orig + g_spine[blockIdx.x];
    if (i < NN) { g_off[i] = excl; g_pos[i] = excl; }
}

__global__ void k_scatter(const void* __restrict__ ei) {
    int e = blockIdx.x * blockDim.x + threadIdx.x;
    if (e >= NE) return;
    int s, d;
    if (g_is64) {
        const long long* p = (const long long*)ei;
        s = (int)p[e]; d = (int)p[NE + e];
    } else {
        const int* p = (const int*)ei;
        s = p[e]; d = p[NE + e];
    }
    int pos = atomicAdd(&g_pos[d], 1);
    g_adj[pos] = s;
}

// ---------------- fused GEMM + alpha ------------------------------------------
// 128 threads, 64 nodes/block; thread = 4 nodes x 8 cols.
template <bool FIRST, int H>
__global__ void k_gemm(const float* __restrict__ W,
                       const float* __restrict__ ue,
                       const float* __restrict__ ie,
                       const float* __restrict__ a_src,
                       const float* __restrict__ a_dst) {
    __shared__ float sW[64 * 64];
    __shared__ float sxT[64][68];
    int t = threadIdx.x;
#pragma unroll
    for (int i = 0; i < 8; i++)
        *(float4*)&sW[(t + 128 * i) * 4] = *(const float4*)&W[(t + 128 * i) * 4];
    int n0 = blockIdx.x * 64;
#pragma unroll
    for (int i = 0; i < 8; i++) {
        int f = t + 128 * i;
        int node = f >> 4;
        int col  = (f & 15) * 4;
        int n = n0 + node;
        float4 v = make_float4(0.f, 0.f, 0.f, 0.f);
        if (n < NN) {
            const float* row = FIRST
                ? (n < N_USERS ? ue + (size_t)n * 64
                               : ie + (size_t)(n - N_USERS) * 64)
                : g_x + (size_t)n * 64;
            v = *(const float4*)(row + col);
        }
        sxT[col + 0][node] = v.x; sxT[col + 1][node] = v.y;
        sxT[col + 2][node] = v.z; sxT[col + 3][node] = v.w;
    }
    __syncthreads();
    int ng = t >> 3;
    int cg = t & 7;
    float acc[4][8];
#pragma unroll
    for (int i = 0; i < 4; i++)
#pragma unroll
        for (int j = 0; j < 8; j++) acc[i][j] = 0.f;
#pragma unroll 4
    for (int k = 0; k < 64; k++) {
        float4 xv = *(float4*)&sxT[k][ng * 4];
        float4 w0 = *(float4*)&sW[k * 64 + cg * 8];
        float4 w1 = *(float4*)&sW[k * 64 + cg * 8 + 4];
        float xi;
#pragma unroll
        for (int i = 0; i < 4; i++) {
            xi = (i == 0) ? xv.x : (i == 1) ? xv.y : (i == 2) ? xv.z : xv.w;
            acc[i][0] += xi * w0.x; acc[i][1] += xi * w0.y;
            acc[i][2] += xi * w0.z; acc[i][3] += xi * w0.w;
            acc[i][4] += xi * w1.x; acc[i][5] += xi * w1.y;
            acc[i][6] += xi * w1.z; acc[i][7] += xi * w1.w;
        }
    }
#pragma unroll
    for (int i = 0; i < 4; i++) {
        int n = n0 + ng * 4 + i;
        if (n < NN) {
            __nv_bfloat162 b0 = __float22bfloat162_rn(make_float2(acc[i][0], acc[i][1]));
            __nv_bfloat162 b1 = __float22bfloat162_rn(make_float2(acc[i][2], acc[i][3]));
            __nv_bfloat162 b2 = __float22bfloat162_rn(make_float2(acc[i][4], acc[i][5]));
            __nv_bfloat162 b3 = __float22bfloat162_rn(make_float2(acc[i][6], acc[i][7]));
            uint4 pk;
            pk.x = *(unsigned*)&b0; pk.y = *(unsigned*)&b1;
            pk.z = *(unsigned*)&b2; pk.w = *(unsigned*)&b3;
            *(uint4*)&g_hb[(size_t)n * 64 + cg * 8] = pk;
        }
    }
    float4 av0 = *(const float4*)&a_src[cg * 8];
    float4 av1 = *(const float4*)&a_src[cg * 8 + 4];
    float4 dv0 = *(const float4*)&a_dst[cg * 8];
    float4 dv1 = *(const float4*)&a_dst[cg * 8 + 4];
    float ps[4], pd[4];
#pragma unroll
    for (int i = 0; i < 4; i++) {
        ps[i] = acc[i][0]*av0.x + acc[i][1]*av0.y + acc[i][2]*av0.z + acc[i][3]*av0.w
              + acc[i][4]*av1.x + acc[i][5]*av1.y + acc[i][6]*av1.z + acc[i][7]*av1.w;
        pd[i] = acc[i][0]*dv0.x + acc[i][1]*dv0.y + acc[i][2]*dv0.z + acc[i][3]*dv0.w
              + acc[i][4]*dv1.x + acc[i][5]*dv1.y + acc[i][6]*dv1.z + acc[i][7]*dv1.w;
    }
    if (H == 4) {
#pragma unroll
        for (int i = 0; i < 4; i++) {
            ps[i] += __shfl_xor_sync(0xffffffffu, ps[i], 1);
            pd[i] += __shfl_xor_sync(0xffffffffu, pd[i], 1);
        }
        if ((cg & 1) == 0) {
            int head = cg >> 1;
#pragma unroll
            for (int i = 0; i < 4; i++) {
                int n = n0 + ng * 4 + i;
                if (n < NN) {
                    g_as[n * 4 + head] = ps[i];
                    g_ad[n * 4 + head] = pd[i];
                }
            }
        }
    } else {
#pragma unroll
        for (int i = 0; i < 4; i++) {
            ps[i] += __shfl_xor_sync(0xffffffffu, ps[i], 1);
            ps[i] += __shfl_xor_sync(0xffffffffu, ps[i], 2);
            ps[i] += __shfl_xor_sync(0xffffffffu, ps[i], 4);
            pd[i] += __shfl_xor_sync(0xffffffffu, pd[i], 1);
            pd[i] += __shfl_xor_sync(0xffffffffu, pd[i], 2);
            pd[i] += __shfl_xor_sync(0xffffffffu, pd[i], 4);
        }
        if (cg == 0) {
#pragma unroll
            for (int i = 0; i < 4; i++) {
                int n = n0 + ng * 4 + i;
                if (n < NN) { g_as[n] = ps[i]; g_ad[n] = pd[i]; }
            }
        }
    }
}

// ---------------- fused aggregation: 4 nodes/warp, software-pipelined --------
// Round-7 shape (8 accs, uint4 = full 128B row wavefront per node gather),
// natural node order (good inter-block load balance). The neighbor loop is
// 2-stage software pipelined: batch k+1's adj/as/h gathers are issued while
// batch k's FMAs consume already-resolved registers.
template <int H, int F>
__global__ void k_agg(const float* __restrict__ b) {
    int lane = threadIdx.x & 31;
    int wrp  = threadIdx.x >> 5;
    int quad = lane >> 3;
    int l    = lane & 7;
    int n    = blockIdx.x * 32 + wrp * 4 + quad;
    if (n >= NN) return;
    int c0   = l * 8;
    int head = c0 / F;

    float ad_d = __ldg(&g_ad[(size_t)n * H + head]);
    float den  = __expf(lrelu(__ldg(&g_as[(size_t)n * H + head]) + ad_d));
    const uint4* hb = (const uint4*)g_hb;          // row = 8 uint4 (64 bf16)
    uint4 hs = hb[(size_t)n * 8 + l];
    float2 h01 = bf2f(hs.x), h23 = bf2f(hs.y), h45 = bf2f(hs.z), h67 = bf2f(hs.w);
    float a0 = den * h01.x, a1 = den * h01.y, a2 = den * h23.x, a3 = den * h23.y;
    float a4 = den * h45.x, a5 = den * h45.y, a6 = den * h67.x, a7 = den * h67.y;

    int beg = g_off[n], end = g_off[n + 1];
    int j = beg;
    float w[4]; uint4 p[4];
    bool have = (j + 4 <= end);
    if (have) {
        int s[4];
#pragma unroll
        for (int q = 0; q < 4; q++) s[q] = __ldg(&g_adj[j + q]);
#pragma unroll
        for (int q = 0; q < 4; q++)
            w[q] = __expf(lrelu(__ldg(&g_as[(size_t)s[q] * H + head]) + ad_d));
#pragma unroll
        for (int q = 0; q < 4; q++) p[q] = hb[(size_t)s[q] * 8 + l];
    }
    while (have) {
        int jn = j + 4;
        bool haven = (jn + 4 <= end);
        float wn[4]; uint4 pn[4];
        if (haven) {                       // prefetch next batch (independent)
            int sn[4];
#pragma unroll
            for (int q = 0; q < 4; q++) sn[q] = __ldg(&g_adj[jn + q]);
#pragma unroll
            for (int q = 0; q < 4; q++)
                wn[q] = __expf(lrelu(__ldg(&g_as[(size_t)sn[q] * H + head]) + ad_d));
#pragma unroll
            for (int q = 0; q < 4; q++) pn[q] = hb[(size_t)sn[q] * 8 + l];
        }
        // consume current batch (registers already resolved)
#pragma unroll
        for (int q = 0; q < 4; q++) {
            float2 q01 = bf2f(p[q].x), q23 = bf2f(p[q].y);
            float2 q45 = bf2f(p[q].z), q67 = bf2f(p[q].w);
            den += w[q];
            a0 += w[q] * q01.x; a1 += w[q] * q01.y;
            a2 += w[q] * q23.x; a3 += w[q] * q23.y;
            a4 += w[q] * q45.x; a5 += w[q] * q45.y;
            a6 += w[q] * q67.x; a7 += w[q] * q67.y;
        }
        j = jn; have = haven;
        if (haven) {
#pragma unroll
            for (int q = 0; q < 4; q++) { w[q] = wn[q]; p[q] = pn[q]; }
        }
    }
    for (; j < end; j++) {                 // tail (deg % 4)
        int s = __ldg(&g_adj[j]);
        float ww = __expf(lrelu(__ldg(&g_as[(size_t)s * H + head]) + ad_d));
        uint4 pp = hb[(size_t)s * 8 + l];
        float2 q01 = bf2f(pp.x), q23 = bf2f(pp.y), q45 = bf2f(pp.z), q67 = bf2f(pp.w);
        den += ww;
        a0 += ww * q01.x; a1 += ww * q01.y; a2 += ww * q23.x; a3 += ww * q23.y;
        a4 += ww * q45.x; a5 += ww * q45.y; a6 += ww * q67.x; a7 += ww * q67.y;
    }
    float inv = 1.f / den;
    float4 o0, o1;
    o0.x = eluf(a0 * inv + b[c0 + 0]);
    o0.y = eluf(a1 * inv + b[c0 + 1]);
    o0.z = eluf(a2 * inv + b[c0 + 2]);
    o0.w = eluf(a3 * inv + b[c0 + 3]);
    o1.x = eluf(a4 * inv + b[c0 + 4]);
    o1.y = eluf(a5 * inv + b[c0 + 5]);
    o1.z = eluf(a6 * inv + b[c0 + 6]);
    o1.w = eluf(a7 * inv + b[c0 + 7]);
    *(float4*)&g_x[(size_t)n * 64 + c0]     = o0;
    *(float4*)&g_x[(size_t)n * 64 + c0 + 4] = o1;
}

// ---------------- final scoring ----------------------------------------------
__global__ void k_score(const void* __restrict__ bu_, const void* __restrict__ bi_,
                        float* __restrict__ out) {
    int gid = blockIdx.x * blockDim.x + threadIdx.x;
    if (gid >= NB * 8) return;
    int p = gid >> 3, l = gid & 7;
    int u, it;
    if (g_is64) {
        u  = (int)((const long long*)bu_)[p];
        it = (int)((const long long*)bi_)[p];
    } else {
        u  = ((const int*)bu_)[p];
        it = ((const int*)bi_)[p];
    }
    const float* xu = &g_x[(long)u * 64];
    const float* xv = &g_x[((long)it + N_USERS) * 64];
    int o = l * 8;
    float acc = 0.f;
#pragma unroll
    for (int k = 0; k < 8; k++) acc += xu[o + k] * xv[o + k];
    acc += __shfl_xor_sync(0xffffffffu, acc, 1);
    acc += __shfl_xor_sync(0xffffffffu, acc, 2);
    acc += __shfl_xor_sync(0xffffffffu, acc, 4);
    if (l == 0) out[p] = 1.f / (1.f + expf(-acc));
}

// ---------------- host launcher ----------------------------------------------
extern "C" void kernel_launch(void* const* d_in, const int* in_sizes, int n_in,
                              void* d_out, int out_size) {
    const void *edge = nullptr, *bu = nullptr, *bi = nullptr;
    const float *ue = nullptr, *ie = nullptr, *W1 = nullptr, *W2 = nullptr;
    const float* v64[6] = {nullptr, nullptr, nullptr, nullptr, nullptr, nullptr};
    int c64 = 0;
    for (int i = 0; i < n_in; i++) {
        int sz = in_sizes[i];
        if      (sz == 2 * NE)        edge = d_in[i];
        else if (sz == NB)            { if (!bu) bu = d_in[i]; else bi = d_in[i]; }
        else if (sz == N_USERS * DD)  ue = (const float*)d_in[i];
        else if (sz == N_ITEMS * DD)  ie = (const float*)d_in[i];
        else if (sz == DD * DD)       { if (!W1) W1 = (const float*)d_in[i];
                                        else     W2 = (const float*)d_in[i]; }
        else if (sz == 64 && c64 < 6) v64[c64++] = (const float*)d_in[i];
    }
    const float *as1 = v64[0], *ad1 = v64[1], *b1 = v64[2];
    const float *as2 = v64[3], *ad2 = v64[4], *b2 = v64[5];

    const int TB = 256;
    const int EB = (NE + TB - 1) / TB;

    k_init   <<<(NN + TB - 1) / TB, TB>>>((const int*)edge);
    k_count  <<<EB, TB>>>(edge);
    k_s1     <<<SB, 256>>>();
    k_s2     <<<1, 1024>>>();
    k_s3     <<<SB, 256>>>();
    k_scatter<<<EB, TB>>>(edge);

    // ---- layer 1: H=4, F=16 ----
    k_gemm<true, 4> <<<(NN + 63) / 64, 128>>>(W1, ue, ie, as1, ad1);
    k_agg <4, 16>   <<<(NN + 31) / 32, TB>>>(b1);

    // ---- layer 2: H=1, F=64 ----
    k_gemm<false, 1><<<(NN + 63) / 64, 128>>>(W2, nullptr, nullptr, as2, ad2);
    k_agg <1, 64>   <<<(NN + 31) / 32, TB>>>(b2);

    k_score<<<(NB * 8 + TB - 1) / TB, TB>>>(bu, bi, (float*)d_out);
}